// round 1
// baseline (speedup 1.0000x reference)
#include <cuda_runtime.h>
#include <math.h>

#define Bb 8
#define Tt 4096
#define Ee 2048
#define Dd 128
#define SCALE 0.08838834764831843f   // 1/sqrt(128)

// ---------------- scratch (static __device__ globals; no allocations) --------
__device__ float g_q[Bb * Tt * Dd];            // 16.8 MB
__device__ float g_k[Bb * Tt * Dd];
__device__ float g_v[Bb * Tt * Dd];
__device__ float g_P[134217728];               // exp(scores), [B][T_i][T_j], 536.9 MB
__device__ float g_part[8][Bb * Tt];           // column-sum partials (deterministic)
__device__ float g_r[Bb * Tt];                 // reciprocal column sums

// ---------------- QKV projection: C[M=32768, N=128] = X[M,2048] @ W[2048,128]
// grid (512, 2, 3): x = M tile (64), y = N tile (64), z selects Wq/Wk/Wv.
__global__ __launch_bounds__(256) void qkv_kernel(
    const float* __restrict__ x,
    const float* __restrict__ Wq,
    const float* __restrict__ Wk,
    const float* __restrict__ Wv)
{
    const float* W  = (blockIdx.z == 0) ? Wq : (blockIdx.z == 1) ? Wk : Wv;
    float*       out = (blockIdx.z == 0) ? g_q : (blockIdx.z == 1) ? g_k : g_v;

    __shared__ float As[16][65];
    __shared__ float Bs[16][65];

    const int m0 = blockIdx.x * 64;
    const int n0 = blockIdx.y * 64;
    const int tid = threadIdx.x;
    const int tx = tid & 15, ty = tid >> 4;

    float acc[4][4] = {};

    for (int k0 = 0; k0 < Ee; k0 += 16) {
#pragma unroll
        for (int u = 0; u < 4; u++) {
            int idx = tid + u * 256;
            int m = idx >> 4, kk = idx & 15;
            As[kk][m] = x[(size_t)(m0 + m) * Ee + (k0 + kk)];
        }
#pragma unroll
        for (int u = 0; u < 4; u++) {
            int idx = tid + u * 256;
            int n = idx & 63, kk = idx >> 6;
            Bs[kk][n] = W[(size_t)(k0 + kk) * Dd + (n0 + n)];
        }
        __syncthreads();
#pragma unroll
        for (int kk = 0; kk < 16; kk++) {
            float a[4], b[4];
#pragma unroll
            for (int i = 0; i < 4; i++) a[i] = As[kk][ty * 4 + i];
#pragma unroll
            for (int j = 0; j < 4; j++) b[j] = Bs[kk][tx * 4 + j];
#pragma unroll
            for (int i = 0; i < 4; i++)
#pragma unroll
                for (int j = 0; j < 4; j++) acc[i][j] += a[i] * b[j];
        }
        __syncthreads();
    }

#pragma unroll
    for (int i = 0; i < 4; i++)
#pragma unroll
        for (int j = 0; j < 4; j++)
            out[(size_t)(m0 + ty * 4 + i) * Dd + (n0 + tx * 4 + j)] = acc[i][j];
}

// ---------------- Scores: P[b,i,j] = exp(scale * q_i . k_j) for i>=j, else 0.
// grid (64, 64, 8): x = j tile, y = i tile, z = batch. Tiles above diagonal skipped.
__global__ __launch_bounds__(256) void scores_kernel()
{
    const int jt = blockIdx.x, it = blockIdx.y, b = blockIdx.z;
    if (jt > it) return;

    const float* q = g_q + (size_t)b * Tt * Dd;
    const float* k = g_k + (size_t)b * Tt * Dd;
    float*       P = g_P + (size_t)b * Tt * Tt;

    __shared__ float Qs[16][65];
    __shared__ float Ks[16][65];

    const int i0 = it * 64, j0 = jt * 64;
    const int tid = threadIdx.x;
    const int tx = tid & 15, ty = tid >> 4;

    float acc[4][4] = {};

    for (int d0 = 0; d0 < Dd; d0 += 16) {
#pragma unroll
        for (int u = 0; u < 4; u++) {
            int idx = tid + u * 256;
            int r = idx >> 4, c = idx & 15;
            Qs[c][r] = q[(size_t)(i0 + r) * Dd + (d0 + c)];
            Ks[c][r] = k[(size_t)(j0 + r) * Dd + (d0 + c)];
        }
        __syncthreads();
#pragma unroll
        for (int kk = 0; kk < 16; kk++) {
            float a[4], bv[4];
#pragma unroll
            for (int i = 0; i < 4; i++) a[i] = Qs[kk][ty * 4 + i];
#pragma unroll
            for (int j = 0; j < 4; j++) bv[j] = Ks[kk][tx * 4 + j];
#pragma unroll
            for (int i = 0; i < 4; i++)
#pragma unroll
                for (int j = 0; j < 4; j++) acc[i][j] += a[i] * bv[j];
        }
        __syncthreads();
    }

#pragma unroll
    for (int ii = 0; ii < 4; ii++) {
        const int i = i0 + ty * 4 + ii;
#pragma unroll
        for (int jj = 0; jj < 4; jj++) {
            const int j = j0 + tx * 4 + jj;
            float e = (i >= j) ? __expf(acc[ii][jj] * SCALE) : 0.0f;
            P[(size_t)i * Tt + j] = e;
        }
    }
}

// ---------------- Column-sum partials: deterministic 8-way split over i.
// grid (16, 8, 8): x = j group (256 cols), y = i split (512 rows), z = batch.
__global__ __launch_bounds__(256) void colsum_part_kernel()
{
    const int j0    = blockIdx.x * 256;
    const int split = blockIdx.y;
    const int b     = blockIdx.z;
    const int j     = j0 + threadIdx.x;
    const int ibeg  = split * 512;

    float* dst = &g_part[split][b * Tt + j];

    if (ibeg + 512 <= j0) {           // whole split strictly above diagonal for all j in group
        *dst = 0.0f;
        return;
    }

    const float* P = g_P + (size_t)b * Tt * Tt;
    // Above-diagonal entries are 0 (diagonal tiles write 0; never-touched tiles
    // are zero-initialized and never written), so unconditional sums are exact.
    float s0 = 0.f, s1 = 0.f, s2 = 0.f, s3 = 0.f;
#pragma unroll 2
    for (int i = ibeg; i < ibeg + 512; i += 4) {
        s0 += P[(size_t)(i + 0) * Tt + j];
        s1 += P[(size_t)(i + 1) * Tt + j];
        s2 += P[(size_t)(i + 2) * Tt + j];
        s3 += P[(size_t)(i + 3) * Tt + j];
    }
    *dst = (s0 + s1) + (s2 + s3);
}

// ---------------- Finish: r[b,j] = 1 / sum_split partials
__global__ __launch_bounds__(256) void colsum_finish_kernel()
{
    const int idx = blockIdx.x * 256 + threadIdx.x;   // b*Tt + j
    float s = 0.f;
#pragma unroll
    for (int p = 0; p < 8; p++) s += g_part[p][idx];
    g_r[idx] = 1.0f / s;
}

// ---------------- PV: out[b,i,:] = sum_{j<=i} (P[b,i,j] * r[b,j]) * v[b,j,:]
// grid (64, 8): x = i tile (reversed for load balance), y = batch.
__global__ __launch_bounds__(256) void pv_kernel(float* __restrict__ out)
{
    const int it = 63 - blockIdx.x;   // heavy tiles launch first
    const int b  = blockIdx.y;

    const float* P = g_P + (size_t)b * Tt * Tt;
    const float* v = g_v + (size_t)b * Tt * Dd;
    const float* r = g_r + b * Tt;

    __shared__ float Ps[16][65];
    __shared__ float Vs[16][128];

    const int tid = threadIdx.x;
    const int tx = tid & 31;   // d-group (4 floats)
    const int ty = tid >> 5;   // i-group (8 rows)
    const int i0 = it * 64;

    float acc[8][4] = {};

    const int jEnd = i0 + 64;
    for (int j0 = 0; j0 < jEnd; j0 += 16) {
#pragma unroll
        for (int u = 0; u < 4; u++) {
            int idx = tid + u * 256;
            int il = idx >> 4, jl = idx & 15;
            float p = P[(size_t)(i0 + il) * Tt + (j0 + jl)] * r[j0 + jl];
            Ps[jl][il] = p;
        }
#pragma unroll
        for (int u = 0; u < 8; u++) {
            int idx = tid + u * 256;
            int jl = idx >> 7, dl = idx & 127;
            Vs[jl][dl] = v[(size_t)(j0 + jl) * Dd + dl];
        }
        __syncthreads();
#pragma unroll
        for (int kk = 0; kk < 16; kk++) {
            float a[8];
#pragma unroll
            for (int ii = 0; ii < 8; ii++) a[ii] = Ps[kk][ty * 8 + ii];
            float4 bv = *reinterpret_cast<const float4*>(&Vs[kk][tx * 4]);
#pragma unroll
            for (int ii = 0; ii < 8; ii++) {
                acc[ii][0] += a[ii] * bv.x;
                acc[ii][1] += a[ii] * bv.y;
                acc[ii][2] += a[ii] * bv.z;
                acc[ii][3] += a[ii] * bv.w;
            }
        }
        __syncthreads();
    }

    float* o = out + (size_t)b * Tt * Dd;
#pragma unroll
    for (int ii = 0; ii < 8; ii++) {
        float4 val = make_float4(acc[ii][0], acc[ii][1], acc[ii][2], acc[ii][3]);
        *reinterpret_cast<float4*>(&o[(size_t)(i0 + ty * 8 + ii) * Dd + tx * 4]) = val;
    }
}

// ---------------- launch ----------------------------------------------------
extern "C" void kernel_launch(void* const* d_in, const int* in_sizes, int n_in,
                              void* d_out, int out_size)
{
    const float* x  = (const float*)d_in[0];
    const float* Wq = (const float*)d_in[1];
    const float* Wk = (const float*)d_in[2];
    const float* Wv = (const float*)d_in[3];
    float* out = (float*)d_out;

    (void)in_sizes; (void)n_in; (void)out_size;

    qkv_kernel<<<dim3(512, 2, 3), 256>>>(x, Wq, Wk, Wv);
    scores_kernel<<<dim3(64, 64, 8), 256>>>();
    colsum_part_kernel<<<dim3(16, 8, 8), 256>>>();
    colsum_finish_kernel<<<(Bb * Tt) / 256, 256>>>();
    pv_kernel<<<dim3(64, 8), 256>>>(out);
}

// round 2
// speedup vs baseline: 2.6625x; 2.6625x over previous
#include <cuda_runtime.h>
#include <math.h>

#define Bb 8
#define Tt 4096
#define Ee 2048
#define Dd 128
#define SCALE 0.08838834764831843f   // 1/sqrt(128)

// ---------------- scratch (static __device__ globals; no allocations) --------
__device__ float g_q[Bb * Tt * Dd];            // 16.8 MB
__device__ float g_k[Bb * Tt * Dd];
__device__ float g_v[Bb * Tt * Dd];
__device__ float g_P[134217728];               // exp(scores), [B][T_i][T_j], 536.9 MB
__device__ float g_part[8][Bb * Tt];           // column-sum partials (deterministic)
__device__ float g_r[Bb * Tt];                 // reciprocal column sums

// ---------------- helpers ----------------------------------------------------
__device__ __forceinline__ unsigned f2tf32(float f) {
    unsigned u;
    asm("cvt.rna.tf32.f32 %0, %1;" : "=r"(u) : "f"(f));
    return u;
}

// D += A(16x8 tf32) * B(8x8 tf32), f32 accum. row.col layout.
__device__ __forceinline__ void mma_tf32(float c[4], const unsigned a[4], const unsigned b[2]) {
    asm volatile(
        "mma.sync.aligned.m16n8k8.row.col.f32.tf32.tf32.f32 "
        "{%0,%1,%2,%3}, {%4,%5,%6,%7}, {%8,%9}, {%0,%1,%2,%3};\n"
        : "+f"(c[0]), "+f"(c[1]), "+f"(c[2]), "+f"(c[3])
        : "r"(a[0]), "r"(a[1]), "r"(a[2]), "r"(a[3]), "r"(b[0]), "r"(b[1]));
}

// Fragment mapping (m16n8k8 tf32):
//  A: a0=(g, t) a1=(g+8, t) a2=(g, t+4) a3=(g+8, t+4)   [g=lane>>2, t=lane&3]
//  B: b0=(k=t, n=g) b1=(k=t+4, n=g)
//  C: c0=(g, 2t) c1=(g, 2t+1) c2=(g+8, 2t) c3=(g+8, 2t+1)
#define LDA(frag, base, row, col, stride)                       \
    do {                                                         \
        (frag)[0] = (base)[(row) * (stride) + (col)];            \
        (frag)[1] = (base)[((row) + 8) * (stride) + (col)];      \
        (frag)[2] = (base)[(row) * (stride) + (col) + 4];        \
        (frag)[3] = (base)[((row) + 8) * (stride) + (col) + 4];  \
    } while (0)

// ---------------- QKV projection: C[M=32768, N=128] = X[M,2048] @ W[2048,128]
// grid (256, 2, 3): x = M tile (128), y = N tile (64), z selects Wq/Wk/Wv.
// 8 warps as 4(M) x 2(N); warp tile 32x32.
__global__ __launch_bounds__(256) void qkv_kernel(
    const float* __restrict__ x,
    const float* __restrict__ Wq,
    const float* __restrict__ Wk,
    const float* __restrict__ Wv)
{
    const float* W   = (blockIdx.z == 0) ? Wq : (blockIdx.z == 1) ? Wk : Wv;
    float*       out = (blockIdx.z == 0) ? g_q : (blockIdx.z == 1) ? g_k : g_v;

    __shared__ unsigned Xs[128 * 36];   // [m][k] k-chunk 32, stride 36
    __shared__ unsigned Ws[64 * 36];    // [n][k]

    const int m0 = blockIdx.x * 128;
    const int n0 = blockIdx.y * 64;
    const int tid  = threadIdx.x;
    const int lane = tid & 31;
    const int wid  = tid >> 5;
    const int wm = (wid >> 1) * 32;     // warp M origin in block
    const int wn = (wid & 1) * 32;      // warp N origin in block
    const int g = lane >> 2, t = lane & 3;

    float acc[2][4][4] = {};

    for (int k0 = 0; k0 < Ee; k0 += 32) {
        // load X tile 128x32 (4 float4 per thread)
#pragma unroll
        for (int u = 0; u < 4; u++) {
            int idx = tid + u * 256;
            int row = idx >> 3, c4 = idx & 7;
            float4 v4 = *reinterpret_cast<const float4*>(&x[(size_t)(m0 + row) * Ee + k0 + c4 * 4]);
            uint4 uv = make_uint4(f2tf32(v4.x), f2tf32(v4.y), f2tf32(v4.z), f2tf32(v4.w));
            *reinterpret_cast<uint4*>(&Xs[row * 36 + c4 * 4]) = uv;
        }
        // load W tile 32(k)x64(n), transposed into Ws[n][k] (2 float4 per thread)
#pragma unroll
        for (int u = 0; u < 2; u++) {
            int idx = tid + u * 256;
            int kk = idx >> 4, n4 = idx & 15;
            float4 v4 = *reinterpret_cast<const float4*>(&W[(size_t)(k0 + kk) * Dd + n0 + n4 * 4]);
            Ws[(n4 * 4 + 0) * 36 + kk] = f2tf32(v4.x);
            Ws[(n4 * 4 + 1) * 36 + kk] = f2tf32(v4.y);
            Ws[(n4 * 4 + 2) * 36 + kk] = f2tf32(v4.z);
            Ws[(n4 * 4 + 3) * 36 + kk] = f2tf32(v4.w);
        }
        __syncthreads();
#pragma unroll
        for (int ks = 0; ks < 4; ks++) {
            const int kc = ks * 8;
            unsigned a[2][4], b[4][2];
#pragma unroll
            for (int mi = 0; mi < 2; mi++)
                LDA(a[mi], Xs, wm + mi * 16 + g, kc + t, 36);
#pragma unroll
            for (int ni = 0; ni < 4; ni++) {
                int n = wn + ni * 8 + g;
                b[ni][0] = Ws[n * 36 + kc + t];
                b[ni][1] = Ws[n * 36 + kc + 4 + t];
            }
#pragma unroll
            for (int mi = 0; mi < 2; mi++)
#pragma unroll
                for (int ni = 0; ni < 4; ni++)
                    mma_tf32(acc[mi][ni], a[mi], b[ni]);
        }
        __syncthreads();
    }

#pragma unroll
    for (int mi = 0; mi < 2; mi++)
#pragma unroll
        for (int ni = 0; ni < 4; ni++) {
            int i = m0 + wm + mi * 16 + g;
            int j = n0 + wn + ni * 8 + t * 2;
            *reinterpret_cast<float2*>(&out[(size_t)i * Dd + j]) =
                make_float2(acc[mi][ni][0], acc[mi][ni][1]);
            *reinterpret_cast<float2*>(&out[(size_t)(i + 8) * Dd + j]) =
                make_float2(acc[mi][ni][2], acc[mi][ni][3]);
        }
}

// ---------------- Scores: P[b,i,j] = exp(scale * q_i . k_j) for i>=j, else 0.
// grid (32, 32, 8): x = j tile(128), y = i tile(128), z = batch; jt > it skipped.
// 8 warps as 4(M=i) x 2(N=j); warp tile 32x64.
__global__ __launch_bounds__(256) void scores_kernel()
{
    const int jt = blockIdx.x, it = blockIdx.y, b = blockIdx.z;
    if (jt > it) return;

    const float* q = g_q + (size_t)b * Tt * Dd;
    const float* k = g_k + (size_t)b * Tt * Dd;
    float*       P = g_P + (size_t)b * Tt * Tt;

    __shared__ unsigned Qs[128 * 36];
    __shared__ unsigned Ks[128 * 36];

    const int i0 = it * 128, j0 = jt * 128;
    const int tid  = threadIdx.x;
    const int lane = tid & 31;
    const int wid  = tid >> 5;
    const int wm = (wid >> 1) * 32;
    const int wn = (wid & 1) * 64;
    const int g = lane >> 2, t = lane & 3;

    float acc[2][8][4] = {};

    for (int d0 = 0; d0 < Dd; d0 += 32) {
#pragma unroll
        for (int u = 0; u < 4; u++) {
            int idx = tid + u * 256;
            int row = idx >> 3, c4 = idx & 7;
            float4 vq = *reinterpret_cast<const float4*>(&q[(size_t)(i0 + row) * Dd + d0 + c4 * 4]);
            float4 vk = *reinterpret_cast<const float4*>(&k[(size_t)(j0 + row) * Dd + d0 + c4 * 4]);
            *reinterpret_cast<uint4*>(&Qs[row * 36 + c4 * 4]) =
                make_uint4(f2tf32(vq.x), f2tf32(vq.y), f2tf32(vq.z), f2tf32(vq.w));
            *reinterpret_cast<uint4*>(&Ks[row * 36 + c4 * 4]) =
                make_uint4(f2tf32(vk.x), f2tf32(vk.y), f2tf32(vk.z), f2tf32(vk.w));
        }
        __syncthreads();
#pragma unroll
        for (int ks = 0; ks < 4; ks++) {
            const int kc = ks * 8;
            unsigned a[2][4], bf[8][2];
#pragma unroll
            for (int mi = 0; mi < 2; mi++)
                LDA(a[mi], Qs, wm + mi * 16 + g, kc + t, 36);
#pragma unroll
            for (int ni = 0; ni < 8; ni++) {
                int n = wn + ni * 8 + g;
                bf[ni][0] = Ks[n * 36 + kc + t];
                bf[ni][1] = Ks[n * 36 + kc + 4 + t];
            }
#pragma unroll
            for (int mi = 0; mi < 2; mi++)
#pragma unroll
                for (int ni = 0; ni < 8; ni++)
                    mma_tf32(acc[mi][ni], a[mi], bf[ni]);
        }
        __syncthreads();
    }

#pragma unroll
    for (int mi = 0; mi < 2; mi++)
#pragma unroll
        for (int ni = 0; ni < 8; ni++) {
            int i = i0 + wm + mi * 16 + g;
            int j = j0 + wn + ni * 8 + t * 2;
            float e0 = (i >= j)     ? __expf(acc[mi][ni][0] * SCALE) : 0.0f;
            float e1 = (i >= j + 1) ? __expf(acc[mi][ni][1] * SCALE) : 0.0f;
            *reinterpret_cast<float2*>(&P[(size_t)i * Tt + j]) = make_float2(e0, e1);
            int i2 = i + 8;
            float e2 = (i2 >= j)     ? __expf(acc[mi][ni][2] * SCALE) : 0.0f;
            float e3 = (i2 >= j + 1) ? __expf(acc[mi][ni][3] * SCALE) : 0.0f;
            *reinterpret_cast<float2*>(&P[(size_t)i2 * Tt + j]) = make_float2(e2, e3);
        }
}

// ---------------- Column-sum partials: deterministic 8-way split over i.
// grid (16, 8, 8): x = j group (256 cols), y = i split (512 rows), z = batch.
__global__ __launch_bounds__(256) void colsum_part_kernel()
{
    const int j0    = blockIdx.x * 256;
    const int split = blockIdx.y;
    const int b     = blockIdx.z;
    const int j     = j0 + threadIdx.x;
    const int ibeg  = split * 512;

    float* dst = &g_part[split][b * Tt + j];

    if (ibeg + 512 <= j0) {           // split entirely above diagonal for all j in group
        *dst = 0.0f;
        return;
    }

    const float* P = g_P + (size_t)b * Tt * Tt;
    // rows i < j0 contribute only zeros for this j-group; skip them.
    const int istart = (ibeg > j0) ? ibeg : j0;
    float s0 = 0.f, s1 = 0.f, s2 = 0.f, s3 = 0.f;
#pragma unroll 2
    for (int i = istart; i < ibeg + 512; i += 4) {
        s0 += P[(size_t)(i + 0) * Tt + j];
        s1 += P[(size_t)(i + 1) * Tt + j];
        s2 += P[(size_t)(i + 2) * Tt + j];
        s3 += P[(size_t)(i + 3) * Tt + j];
    }
    *dst = (s0 + s1) + (s2 + s3);
}

// ---------------- Finish: r[b,j] = 1 / sum_split partials
__global__ __launch_bounds__(256) void colsum_finish_kernel()
{
    const int idx = blockIdx.x * 256 + threadIdx.x;   // b*Tt + j
    float s = 0.f;
#pragma unroll
    for (int p = 0; p < 8; p++) s += g_part[p][idx];
    g_r[idx] = 1.0f / s;
}

// ---------------- PV: out[b,i,:] = sum_{j<=i} (P[b,i,j] * r[b,j]) * v[b,j,:]
// grid (64, 8): x = i tile (64, reversed for balance), y = batch.
// 8 warps as 2(M=i) x 4(N=d); warp tile 32x32.
__global__ __launch_bounds__(256) void pv_kernel(float* __restrict__ out)
{
    const int it = 63 - blockIdx.x;
    const int b  = blockIdx.y;

    const float* P = g_P + (size_t)b * Tt * Tt;
    const float* v = g_v + (size_t)b * Tt * Dd;
    const float* r = g_r + b * Tt;

    __shared__ unsigned Ps[64 * 36];     // [i][j-chunk 32]
    __shared__ unsigned Vs[32 * 136];    // [j][d 128], stride 136

    const int tid  = threadIdx.x;
    const int lane = tid & 31;
    const int wid  = tid >> 5;
    const int wm = (wid >> 2) * 32;      // i
    const int wn = (wid & 3) * 32;       // d
    const int g = lane >> 2, t = lane & 3;
    const int i0 = it * 64;

    float acc[2][4][4] = {};

    const int jEnd = i0 + 64;
    for (int j0 = 0; j0 < jEnd; j0 += 32) {
        // load P tile 64x32, fold in r[j]  (2 float4 per thread)
#pragma unroll
        for (int u = 0; u < 2; u++) {
            int idx = tid + u * 256;
            int row = idx >> 3, c4 = idx & 7;
            int j = j0 + c4 * 4;
            float4 p4 = *reinterpret_cast<const float4*>(&P[(size_t)(i0 + row) * Tt + j]);
            float4 r4 = *reinterpret_cast<const float4*>(&r[j]);
            *reinterpret_cast<uint4*>(&Ps[row * 36 + c4 * 4]) =
                make_uint4(f2tf32(p4.x * r4.x), f2tf32(p4.y * r4.y),
                           f2tf32(p4.z * r4.z), f2tf32(p4.w * r4.w));
        }
        // load V tile 32(j)x128(d)  (4 float4 per thread)
#pragma unroll
        for (int u = 0; u < 4; u++) {
            int idx = tid + u * 256;
            int jl = idx >> 5, d4 = idx & 31;
            float4 v4 = *reinterpret_cast<const float4*>(&v[(size_t)(j0 + jl) * Dd + d4 * 4]);
            *reinterpret_cast<uint4*>(&Vs[jl * 136 + d4 * 4]) =
                make_uint4(f2tf32(v4.x), f2tf32(v4.y), f2tf32(v4.z), f2tf32(v4.w));
        }
        __syncthreads();
#pragma unroll
        for (int ks = 0; ks < 4; ks++) {
            const int kc = ks * 8;
            unsigned a[2][4], bf[4][2];
#pragma unroll
            for (int mi = 0; mi < 2; mi++)
                LDA(a[mi], Ps, wm + mi * 16 + g, kc + t, 36);
#pragma unroll
            for (int ni = 0; ni < 4; ni++) {
                int n = wn + ni * 8 + g;
                bf[ni][0] = Vs[(kc + t) * 136 + n];
                bf[ni][1] = Vs[(kc + 4 + t) * 136 + n];
            }
#pragma unroll
            for (int mi = 0; mi < 2; mi++)
#pragma unroll
                for (int ni = 0; ni < 4; ni++)
                    mma_tf32(acc[mi][ni], a[mi], bf[ni]);
        }
        __syncthreads();
    }

    float* o = out + (size_t)b * Tt * Dd;
#pragma unroll
    for (int mi = 0; mi < 2; mi++)
#pragma unroll
        for (int ni = 0; ni < 4; ni++) {
            int i = i0 + wm + mi * 16 + g;
            int d = wn + ni * 8 + t * 2;
            *reinterpret_cast<float2*>(&o[(size_t)i * Dd + d]) =
                make_float2(acc[mi][ni][0], acc[mi][ni][1]);
            *reinterpret_cast<float2*>(&o[(size_t)(i + 8) * Dd + d]) =
                make_float2(acc[mi][ni][2], acc[mi][ni][3]);
        }
}

// ---------------- launch ----------------------------------------------------
extern "C" void kernel_launch(void* const* d_in, const int* in_sizes, int n_in,
                              void* d_out, int out_size)
{
    const float* x  = (const float*)d_in[0];
    const float* Wq = (const float*)d_in[1];
    const float* Wk = (const float*)d_in[2];
    const float* Wv = (const float*)d_in[3];
    float* out = (float*)d_out;

    (void)in_sizes; (void)n_in; (void)out_size;

    qkv_kernel<<<dim3(256, 2, 3), 256>>>(x, Wq, Wk, Wv);
    scores_kernel<<<dim3(32, 32, 8), 256>>>();
    colsum_part_kernel<<<dim3(16, 8, 8), 256>>>();
    colsum_finish_kernel<<<(Bb * Tt) / 256, 256>>>();
    pv_kernel<<<dim3(64, 8), 256>>>(out);
}